// round 1
// baseline (speedup 1.0000x reference)
#include <cuda_runtime.h>

#define T16K 16384
#define NB 16
#define NC 32
#define NL 30
#define TFIN 13315        // 16384 - 3069
#define OFFF 3069         // total receptive field offset
#define HSTR 13344        // padded stride for h / skip buffers (mult of 32)
#define TILE 128

typedef unsigned long long u64;

// ---------------- scratch (static device globals; allocation-free) -----------
__device__ float g_x0[(size_t)NB * NC * T16K];
__device__ float g_x1[(size_t)NB * NC * T16K];
__device__ float g_h[(size_t)NL * NB * NC * HSTR];   // gated outputs, tail-aligned
__device__ float g_sk[(size_t)NB * 256 * HSTR];      // relu(skip-sum)

// ---------------- packed f32x2 helpers ---------------------------------------
__device__ __forceinline__ u64 pack2(float x, float y) {
    u64 r; asm("mov.b64 %0, {%1, %2};" : "=l"(r) : "f"(x), "f"(y)); return r;
}
__device__ __forceinline__ u64 pack1(float x) { return pack2(x, x); }
__device__ __forceinline__ u64 fma2(u64 a, u64 b, u64 c) {
    u64 d; asm("fma.rn.f32x2 %0, %1, %2, %3;" : "=l"(d) : "l"(a), "l"(b), "l"(c)); return d;
}
__device__ __forceinline__ float2 unpack2(u64 v) {
    float2 f; asm("mov.b64 {%0, %1}, %2;" : "=f"(f.x), "=f"(f.y) : "l"(v)); return f;
}
__device__ __forceinline__ float sigf(float x) {
    return __fdividef(1.f, 1.f + __expf(-x));
}

// ---------------- causal 1x1 conv (1 -> 32 ch) --------------------------------
__global__ void causal_kernel(const float* __restrict__ y,
                              const float* __restrict__ cw,
                              const float* __restrict__ cb) {
    int idx = blockIdx.x * 256 + threadIdx.x;
    if (idx >= NB * NC * T16K) return;
    int g = idx & (T16K - 1);
    int c = (idx >> 14) & 31;
    int b = idx >> 19;
    g_x0[idx] = cw[c] * y[(b << 14) + g] + cb[c];
}

// ---------------- one WaveNet layer (filt/gate/res, stores h) ------------------
// out[g] (g >= off) :  pre_f = sum_ci Wf0*x[g-d] + Wf1*x[g]
//                      h     = tanh(pre_f) * sigmoid(pre_g)
//                      x'    = Wr @ h + x[g]
__global__ void __launch_bounds__(256) layer_kernel(
    const float* __restrict__ fw, const float* __restrict__ gw,
    const float* __restrict__ rw,
    int layer, int d, int off, int parity)
{
    extern __shared__ char smraw[];
    u64*   wf0p = (u64*)smraw;                 // 1024 u64 (both halves = w)
    u64*   wf1p = wf0p + 1024;
    u64*   wg0p = wf1p + 1024;
    u64*   wg1p = wg0p + 1024;
    float* wrs  = (float*)(wg1p + 1024);       // 1024 floats [ci][co]
    float* xs   = wrs + 1024;                  // [32][TILE]  x at g
    float* xsd  = xs + NC * TILE;              // [32][TILE]  x at g-d
    float* hs   = xsd + NC * TILE;             // [TILE][33]  gated out
    float* xns  = hs + TILE * 33;              // [TILE][33]  new x

    const float* xin = parity ? g_x1 : g_x0;
    float*       xout = parity ? g_x0 : g_x1;

    int tid = threadIdx.x;
    int b   = blockIdx.y;
    int g0  = off + blockIdx.x * TILE;

    // stage weights (packed both-halves for f32x2)
    const float* fwb = fw + layer * 2048;
    const float* gwb = gw + layer * 2048;
    for (int idx = tid; idx < 2048; idx += 256) {
        float fv = fwb[idx], gv = gwb[idx];
        int k = idx & 1, ci = (idx >> 1) & 31, co = idx >> 6;
        u64 fp = pack1(fv), gp = pack1(gv);
        if (k == 0) { wf0p[ci * 32 + co] = fp; wg0p[ci * 32 + co] = gp; }
        else        { wf1p[ci * 32 + co] = fp; wg1p[ci * 32 + co] = gp; }
    }
    const float* rwb = rw + layer * 1024;
    for (int idx = tid; idx < 1024; idx += 256) {
        int ci = idx & 31, co = idx >> 5;
        wrs[ci * 32 + co] = rwb[idx];
    }
    // stage x tiles
    const float* xb = xin + (size_t)b * NC * T16K;
    for (int idx = tid; idx < NC * TILE; idx += 256) {
        int ci = idx >> 7, tt = idx & (TILE - 1);
        int g = g0 + tt;
        float v0 = 0.f, v1 = 0.f;
        if (g < T16K) { v1 = xb[ci * T16K + g]; v0 = xb[ci * T16K + g - d]; }
        xs[ci * TILE + tt]  = v1;
        xsd[ci * TILE + tt] = v0;
    }
    __syncthreads();

    int co  = tid & 31;
    int wgi = tid >> 5;

    // phase 1: filt/gate conv + activations, packed f32x2 over time pairs
    for (int it = 0; it < 4; it++) {
        int t0 = (wgi + 8 * it) << 2;
        u64 af0 = 0, af1 = 0, ag0 = 0, ag1 = 0;
#pragma unroll
        for (int ci = 0; ci < 32; ci++) {
            u64 w0 = wf0p[ci * 32 + co], w1 = wf1p[ci * 32 + co];
            u64 v0 = wg0p[ci * 32 + co], v1 = wg1p[ci * 32 + co];
            ulonglong2 x1v = *(const ulonglong2*)&xs[ci * TILE + t0];
            ulonglong2 x0v = *(const ulonglong2*)&xsd[ci * TILE + t0];
            af0 = fma2(w0, x0v.x, af0); af0 = fma2(w1, x1v.x, af0);
            af1 = fma2(w0, x0v.y, af1); af1 = fma2(w1, x1v.y, af1);
            ag0 = fma2(v0, x0v.x, ag0); ag0 = fma2(v1, x1v.x, ag0);
            ag1 = fma2(v0, x0v.y, ag1); ag1 = fma2(v1, x1v.y, ag1);
        }
        float2 f01 = unpack2(af0), f23 = unpack2(af1);
        float2 s01 = unpack2(ag0), s23 = unpack2(ag1);
        hs[(t0 + 0) * 33 + co] = tanhf(f01.x) * sigf(s01.x);
        hs[(t0 + 1) * 33 + co] = tanhf(f01.y) * sigf(s01.y);
        hs[(t0 + 2) * 33 + co] = tanhf(f23.x) * sigf(s23.x);
        hs[(t0 + 3) * 33 + co] = tanhf(f23.y) * sigf(s23.y);
    }
    __syncthreads();

    // phase 2: res 1x1 conv + residual add
    for (int it = 0; it < 4; it++) {
        int t0 = (wgi + 8 * it) << 2;
        float4 acc = *(const float4*)&xs[co * TILE + t0];
#pragma unroll
        for (int ci = 0; ci < 32; ci++) {
            float w = wrs[ci * 32 + co];
            acc.x += w * hs[(t0 + 0) * 33 + ci];
            acc.y += w * hs[(t0 + 1) * 33 + ci];
            acc.z += w * hs[(t0 + 2) * 33 + ci];
            acc.w += w * hs[(t0 + 3) * 33 + ci];
        }
        xns[(t0 + 0) * 33 + co] = acc.x;
        xns[(t0 + 1) * 33 + co] = acc.y;
        xns[(t0 + 2) * 33 + co] = acc.z;
        xns[(t0 + 3) * 33 + co] = acc.w;
    }
    __syncthreads();

    // coalesced global stores
    float* xob = xout + (size_t)b * NC * T16K;
    float* hob = g_h + ((size_t)layer * NB + b) * NC * HSTR;
    for (int idx = tid; idx < NC * TILE; idx += 256) {
        int ci = idx >> 7, tt = idx & (TILE - 1);
        int g = g0 + tt;
        if (g < T16K) {
            xob[ci * T16K + g] = xns[tt * 33 + ci];
            if (g >= OFFF) hob[ci * HSTR + (g - OFFF)] = hs[tt * 33 + ci];
        }
    }
}

// ---------------- skip sum: relu( sum_L SW_L @ h_L )  (256 x 960 GEMM) --------
__global__ void __launch_bounds__(256) skip_kernel(const float* __restrict__ sw)
{
    __shared__ __align__(16) float sws[32 * 260];  // [k][so] padded
    __shared__ __align__(16) float hsm[32 * 68];   // [k][tf] padded

    int tid = threadIdx.x;
    int sx = tid & 31, ty = tid >> 5;   // sx: 8-so group, ty: 8-tf group
    int b   = blockIdx.y;
    int tf0 = blockIdx.x * 64;

    u64 acc[8][4];
#pragma unroll
    for (int i = 0; i < 8; i++)
#pragma unroll
        for (int j = 0; j < 4; j++) acc[i][j] = 0ull;

    for (int L = 0; L < NL; L++) {
        __syncthreads();
        const float* swb = sw + L * 8192;
        for (int idx = tid; idx < 8192; idx += 256) {
            int so = idx >> 5, ci = idx & 31;
            sws[ci * 260 + so] = swb[idx];
        }
        const float* hb = g_h + ((size_t)L * NB + b) * NC * HSTR + tf0;
        for (int idx = tid; idx < 2048; idx += 256) {
            int ci = idx >> 6, tt = idx & 63;
            hsm[ci * 68 + tt] = (tf0 + tt < TFIN) ? hb[ci * HSTR + tt] : 0.f;
        }
        __syncthreads();
#pragma unroll 4
        for (int kk = 0; kk < 32; kk++) {
            float4 a0 = *(const float4*)&sws[kk * 260 + sx * 8];
            float4 a1 = *(const float4*)&sws[kk * 260 + sx * 8 + 4];
            ulonglong2 b01 = *(const ulonglong2*)&hsm[kk * 68 + ty * 8];
            ulonglong2 b23 = *(const ulonglong2*)&hsm[kk * 68 + ty * 8 + 4];
            u64 ap[8] = { pack1(a0.x), pack1(a0.y), pack1(a0.z), pack1(a0.w),
                          pack1(a1.x), pack1(a1.y), pack1(a1.z), pack1(a1.w) };
            u64 bp[4] = { b01.x, b01.y, b23.x, b23.y };
#pragma unroll
            for (int jj = 0; jj < 8; jj++)
#pragma unroll
                for (int p = 0; p < 4; p++)
                    acc[jj][p] = fma2(ap[jj], bp[p], acc[jj][p]);
        }
    }

    float* skb = g_sk + (size_t)b * 256 * HSTR;
    bool full = (tf0 + 64 <= TFIN);
#pragma unroll
    for (int jj = 0; jj < 8; jj++) {
        int so = sx * 8 + jj;
        float v[8];
#pragma unroll
        for (int p = 0; p < 4; p++) {
            float2 f = unpack2(acc[jj][p]);
            v[2 * p]     = fmaxf(f.x, 0.f);
            v[2 * p + 1] = fmaxf(f.y, 0.f);
        }
        if (full) {
            *(float4*)&skb[so * HSTR + tf0 + ty * 8]     = make_float4(v[0], v[1], v[2], v[3]);
            *(float4*)&skb[so * HSTR + tf0 + ty * 8 + 4] = make_float4(v[4], v[5], v[6], v[7]);
        } else {
            for (int j = 0; j < 8; j++) {
                int tf = tf0 + ty * 8 + j;
                if (tf < TFIN) skb[so * HSTR + tf] = v[j];
            }
        }
    }
}

// ---------------- fused end: out = W2 @ relu(W1 @ sk + b1) + b2 ----------------
__global__ void __launch_bounds__(256) end_kernel(
    const float* __restrict__ w1, const float* __restrict__ b1,
    const float* __restrict__ w2, const float* __restrict__ b2,
    float* __restrict__ out)
{
    extern __shared__ char smraw[];
    float* ws   = (float*)smraw;        // 32*260 [k][o]
    float* hsm  = ws + 32 * 260;        // 32*68  [k][tf]
    float* mids = hsm + 32 * 68;        // 64*264 midT[tf][c]

    int tid = threadIdx.x;
    int sx = tid & 31, ty = tid >> 5;
    int b   = blockIdx.y;
    int tf0 = blockIdx.x * 64;

    u64 acc[8][4];
#pragma unroll
    for (int i = 0; i < 8; i++)
#pragma unroll
        for (int j = 0; j < 4; j++) acc[i][j] = 0ull;

    const float* skb = g_sk + (size_t)b * 256 * HSTR + tf0;

    // ---- phase A: mid = relu(W1 @ sk + b1)
    for (int c0 = 0; c0 < 256; c0 += 32) {
        __syncthreads();
        for (int idx = tid; idx < 8192; idx += 256) {
            int o = idx >> 5, c = idx & 31;
            ws[c * 260 + o] = w1[o * 256 + c0 + c];
        }
        for (int idx = tid; idx < 2048; idx += 256) {
            int c = idx >> 6, tt = idx & 63;
            hsm[c * 68 + tt] = (tf0 + tt < TFIN) ? skb[(size_t)(c0 + c) * HSTR + tt] : 0.f;
        }
        __syncthreads();
#pragma unroll 4
        for (int kk = 0; kk < 32; kk++) {
            float4 a0 = *(const float4*)&ws[kk * 260 + sx * 8];
            float4 a1 = *(const float4*)&ws[kk * 260 + sx * 8 + 4];
            ulonglong2 b01 = *(const ulonglong2*)&hsm[kk * 68 + ty * 8];
            ulonglong2 b23 = *(const ulonglong2*)&hsm[kk * 68 + ty * 8 + 4];
            u64 ap[8] = { pack1(a0.x), pack1(a0.y), pack1(a0.z), pack1(a0.w),
                          pack1(a1.x), pack1(a1.y), pack1(a1.z), pack1(a1.w) };
            u64 bp[4] = { b01.x, b01.y, b23.x, b23.y };
#pragma unroll
            for (int jj = 0; jj < 8; jj++)
#pragma unroll
                for (int p = 0; p < 4; p++)
                    acc[jj][p] = fma2(ap[jj], bp[p], acc[jj][p]);
        }
    }
    // bias + relu -> midT[tf][o]
#pragma unroll
    for (int jj = 0; jj < 8; jj++) {
        int o = sx * 8 + jj;
        float bias = b1[o];
#pragma unroll
        for (int p = 0; p < 4; p++) {
            float2 f = unpack2(acc[jj][p]);
            mids[(ty * 8 + 2 * p)     * 264 + o] = fmaxf(f.x + bias, 0.f);
            mids[(ty * 8 + 2 * p + 1) * 264 + o] = fmaxf(f.y + bias, 0.f);
        }
    }

    // ---- phase B: out = W2 @ mid + b2
    u64 acc2[8][4];
#pragma unroll
    for (int i = 0; i < 8; i++)
#pragma unroll
        for (int j = 0; j < 4; j++) acc2[i][j] = 0ull;

    for (int c0 = 0; c0 < 256; c0 += 32) {
        __syncthreads();
        for (int idx = tid; idx < 8192; idx += 256) {
            int o = idx >> 5, c = idx & 31;
            ws[c * 260 + o] = w2[o * 256 + c0 + c];
        }
        __syncthreads();
#pragma unroll 4
        for (int kk = 0; kk < 32; kk++) {
            float4 a0 = *(const float4*)&ws[kk * 260 + sx * 8];
            float4 a1 = *(const float4*)&ws[kk * 260 + sx * 8 + 4];
            int c = c0 + kk;
            float h0 = mids[(ty * 8 + 0) * 264 + c];
            float h1 = mids[(ty * 8 + 1) * 264 + c];
            float h2 = mids[(ty * 8 + 2) * 264 + c];
            float h3 = mids[(ty * 8 + 3) * 264 + c];
            float h4 = mids[(ty * 8 + 4) * 264 + c];
            float h5 = mids[(ty * 8 + 5) * 264 + c];
            float h6 = mids[(ty * 8 + 6) * 264 + c];
            float h7 = mids[(ty * 8 + 7) * 264 + c];
            u64 ap[8] = { pack1(a0.x), pack1(a0.y), pack1(a0.z), pack1(a0.w),
                          pack1(a1.x), pack1(a1.y), pack1(a1.z), pack1(a1.w) };
            u64 bp[4] = { pack2(h0, h1), pack2(h2, h3), pack2(h4, h5), pack2(h6, h7) };
#pragma unroll
            for (int jj = 0; jj < 8; jj++)
#pragma unroll
                for (int p = 0; p < 4; p++)
                    acc2[jj][p] = fma2(ap[jj], bp[p], acc2[jj][p]);
        }
    }
    // bias + store to output (true [16,256,13315] layout)
#pragma unroll
    for (int jj = 0; jj < 8; jj++) {
        int o = sx * 8 + jj;
        float bias = b2[o];
        float* ob = out + ((size_t)b * 256 + o) * TFIN;
#pragma unroll
        for (int p = 0; p < 4; p++) {
            float2 f = unpack2(acc2[jj][p]);
            int tf = tf0 + ty * 8 + 2 * p;
            if (tf < TFIN)     ob[tf]     = f.x + bias;
            if (tf + 1 < TFIN) ob[tf + 1] = f.y + bias;
        }
    }
}

#define LAYER_SMEM (4 * 1024 * 8 + (1024 + 2 * 32 * 128 + 2 * 128 * 33) * 4)
#define END_SMEM   ((32 * 260 + 32 * 68 + 64 * 264) * 4)

extern "C" void kernel_launch(void* const* d_in, const int* in_sizes, int n_in,
                              void* d_out, int out_size)
{
    const float* y   = (const float*)d_in[0];
    const float* cw  = (const float*)d_in[1];
    const float* cb  = (const float*)d_in[2];
    const float* fw  = (const float*)d_in[3];
    const float* gw  = (const float*)d_in[4];
    const float* rw  = (const float*)d_in[5];
    const float* sw  = (const float*)d_in[6];
    const float* e1w = (const float*)d_in[7];
    const float* e1b = (const float*)d_in[8];
    const float* e2w = (const float*)d_in[9];
    const float* e2b = (const float*)d_in[10];
    float* out = (float*)d_out;

    cudaFuncSetAttribute(layer_kernel, cudaFuncAttributeMaxDynamicSharedMemorySize, LAYER_SMEM);
    cudaFuncSetAttribute(end_kernel,   cudaFuncAttributeMaxDynamicSharedMemorySize, END_SMEM);

    causal_kernel<<<(NB * NC * T16K + 255) / 256, 256>>>(y, cw, cb);

    int off = 0, parity = 0;
    for (int i = 0; i < NL; i++) {
        int d = 1 << (i % 10);
        off += d;
        int nbx = (T16K - off + TILE - 1) / TILE;
        layer_kernel<<<dim3(nbx, NB), 256, LAYER_SMEM>>>(fw, gw, rw, i, d, off, parity);
        parity ^= 1;
    }

    int ntf = (TFIN + 63) / 64;
    skip_kernel<<<dim3(ntf, NB), 256>>>(sw);
    end_kernel<<<dim3(ntf, NB), 256, END_SMEM>>>(e1w, e1b, e2w, e2b, out);
}

// round 3
// speedup vs baseline: 1.1652x; 1.1652x over previous
#include <cuda_runtime.h>

#define T16K 16384
#define NB 16
#define NC 32
#define NL 30
#define TFIN 13315        // 16384 - 3069
#define OFFF 3069         // total receptive field
#define HSTR 13344        // h time-stride (mult of 32)
#define SKT  13320        // sk time-stride (mult of 8)
#define LTILE 64

typedef unsigned long long u64;

// ---------------- scratch (static device globals; allocation-free) -----------
__device__ float g_x0[(size_t)NB * T16K * NC];
__device__ float g_x1[(size_t)NB * T16K * NC];
__device__ float g_h [(size_t)NL * NB * HSTR * NC];   // [L][b][t][32]
__device__ float g_sk[(size_t)NB * SKT * 256];        // [b][t][256]

// ---------------- packed f32x2 helpers ---------------------------------------
__device__ __forceinline__ u64 pack2(float x, float y) {
    u64 r; asm("mov.b64 %0, {%1, %2};" : "=l"(r) : "f"(x), "f"(y)); return r;
}
__device__ __forceinline__ u64 pack1(float x) { return pack2(x, x); }
__device__ __forceinline__ u64 fma2(u64 a, u64 b, u64 c) {
    u64 d; asm("fma.rn.f32x2 %0, %1, %2, %3;" : "=l"(d) : "l"(a), "l"(b), "l"(c)); return d;
}
__device__ __forceinline__ float2 unpack2(u64 v) {
    float2 f; asm("mov.b64 {%0, %1}, %2;" : "=f"(f.x), "=f"(f.y) : "l"(v)); return f;
}
__device__ __forceinline__ float sigf(float x) {
    return __fdividef(1.f, 1.f + __expf(-x));
}
__device__ __forceinline__ float tanh_fast(float x) {
    return 1.f - __fdividef(2.f, 1.f + __expf(2.f * x));
}

// ---------------- causal 1x1 conv (1 -> 32 ch), channel-fastest out -----------
__global__ void causal_kernel(const float* __restrict__ y,
                              const float* __restrict__ cw,
                              const float* __restrict__ cb) {
    int idx = blockIdx.x * 256 + threadIdx.x;
    if (idx >= NB * T16K * NC) return;
    int c = idx & 31;
    int t = (idx >> 5) & (T16K - 1);
    int b = idx >> 19;
    g_x0[idx] = cw[c] * y[(b << 14) + t] + cb[c];
}

// ---------------- one WaveNet layer -------------------------------------------
// x layout [b][t][32]. Block: 64 time steps x 32 co; thread: 4t x 2co.
__global__ void __launch_bounds__(256) layer_kernel(
    const float* __restrict__ fw, const float* __restrict__ gw,
    const float* __restrict__ rw,
    int layer, int d, int off, int parity)
{
    __shared__ __align__(16) u64 wfs[2][16 * 32];   // [k][ci2][co] packed ci-pairs
    __shared__ __align__(16) u64 wgs[2][16 * 32];
    __shared__ __align__(16) u64 wrs[16 * 32];
    __shared__ __align__(16) float xs [LTILE * 32]; // x[g]
    __shared__ __align__(16) float xsd[LTILE * 32]; // x[g-d]; reused as h after ph1

    int tid = threadIdx.x;
    int b   = blockIdx.y;
    int g0  = off + blockIdx.x * LTILE;

    const float* xin  = parity ? g_x1 : g_x0;
    float*       xout = parity ? g_x0 : g_x1;

    // stage weights packed over ci-pairs
    const float* fwb = fw + layer * 2048;    // [co][ci][k]
    const float* gwb = gw + layer * 2048;
    for (int idx = tid; idx < 1024; idx += 256) {
        int co = idx & 31, ci2 = (idx >> 5) & 15, k = idx >> 9;
        int go = co * 64 + ci2 * 4 + k;
        wfs[k][ci2 * 32 + co] = pack2(fwb[go], fwb[go + 2]);
        wgs[k][ci2 * 32 + co] = pack2(gwb[go], gwb[go + 2]);
    }
    const float* rwb = rw + layer * 1024;    // [co][ci]
    for (int idx = tid; idx < 512; idx += 256) {
        int co = idx & 31, ci2 = idx >> 5;
        wrs[ci2 * 32 + co] = pack2(rwb[co * 32 + ci2 * 2], rwb[co * 32 + ci2 * 2 + 1]);
    }
    // stage x tiles (coalesced float4 rows)
    const float* xb = xin + (size_t)b * T16K * NC;
    for (int idx = tid; idx < 512; idx += 256) {
        int tt = idx >> 3, c4 = (idx & 7) * 4;
        int g = g0 + tt;
        float4 v1 = make_float4(0.f, 0.f, 0.f, 0.f), v0 = v1;
        if (g < T16K) {
            v1 = *(const float4*)&xb[(size_t)g * 32 + c4];
            v0 = *(const float4*)&xb[(size_t)(g - d) * 32 + c4];
        }
        *(float4*)&xs [tt * 32 + c4] = v1;
        *(float4*)&xsd[tt * 32 + c4] = v0;
    }
    __syncthreads();

    int co2 = (tid & 15) * 2;
    int t4  = (tid >> 4) * 4;

    // ---- phase 1: filt/gate conv, f32x2 packed over ci pairs
    u64 af[4][2], ag[4][2];
#pragma unroll
    for (int j = 0; j < 4; j++) { af[j][0]=af[j][1]=ag[j][0]=ag[j][1]=0ull; }
    const u64* wf0 = &wfs[0][co2];
    const u64* wf1 = &wfs[1][co2];
    const u64* wg0 = &wgs[0][co2];
    const u64* wg1 = &wgs[1][co2];
    const float* xsp  = &xs [t4 * 32];
    const float* xsdp = &xsd[t4 * 32];
#pragma unroll
    for (int ci2 = 0; ci2 < 16; ci2++) {
        ulonglong2 f0 = *(const ulonglong2*)(wf0 + ci2 * 32);
        ulonglong2 f1 = *(const ulonglong2*)(wf1 + ci2 * 32);
        ulonglong2 q0 = *(const ulonglong2*)(wg0 + ci2 * 32);
        ulonglong2 q1 = *(const ulonglong2*)(wg1 + ci2 * 32);
#pragma unroll
        for (int j = 0; j < 4; j++) {
            u64 x1 = *(const u64*)(xsp  + j * 32 + ci2 * 2);
            u64 x0 = *(const u64*)(xsdp + j * 32 + ci2 * 2);
            af[j][0] = fma2(f0.x, x0, af[j][0]); af[j][0] = fma2(f1.x, x1, af[j][0]);
            af[j][1] = fma2(f0.y, x0, af[j][1]); af[j][1] = fma2(f1.y, x1, af[j][1]);
            ag[j][0] = fma2(q0.x, x0, ag[j][0]); ag[j][0] = fma2(q1.x, x1, ag[j][0]);
            ag[j][1] = fma2(q0.y, x0, ag[j][1]); ag[j][1] = fma2(q1.y, x1, ag[j][1]);
        }
    }
    float hreg[4][2];
#pragma unroll
    for (int j = 0; j < 4; j++)
#pragma unroll
        for (int c = 0; c < 2; c++) {
            float2 fv = unpack2(af[j][c]);
            float2 gv = unpack2(ag[j][c]);
            hreg[j][c] = tanh_fast(fv.x + fv.y) * sigf(gv.x + gv.y);
        }
    __syncthreads();                // all reads of xsd done
    float* hs = xsd;                // reuse as h buffer
#pragma unroll
    for (int j = 0; j < 4; j++)
        *(float2*)&hs[(t4 + j) * 32 + co2] = make_float2(hreg[j][0], hreg[j][1]);
    __syncthreads();

    // ---- phase 2: res 1x1 conv + residual, then coalesced stores
    u64 ar[4][2];
#pragma unroll
    for (int j = 0; j < 4; j++) { ar[j][0]=ar[j][1]=0ull; }
    const u64* wrp = &wrs[co2];
    const float* hsp = &hs[t4 * 32];
#pragma unroll
    for (int ci2 = 0; ci2 < 16; ci2++) {
        ulonglong2 wv = *(const ulonglong2*)(wrp + ci2 * 32);
#pragma unroll
        for (int j = 0; j < 4; j++) {
            u64 hv = *(const u64*)(hsp + j * 32 + ci2 * 2);
            ar[j][0] = fma2(wv.x, hv, ar[j][0]);
            ar[j][1] = fma2(wv.y, hv, ar[j][1]);
        }
    }
    float* xob = xout + (size_t)b * T16K * NC;
    float* hob = g_h + (size_t)(layer * NB + b) * HSTR * NC;
#pragma unroll
    for (int j = 0; j < 4; j++) {
        int g = g0 + t4 + j;
        if (g < T16K) {
            float2 r0 = unpack2(ar[j][0]);
            float2 r1 = unpack2(ar[j][1]);
            float xo0 = xs[(t4 + j) * 32 + co2]     + r0.x + r0.y;
            float xo1 = xs[(t4 + j) * 32 + co2 + 1] + r1.x + r1.y;
            *(float2*)&xob[(size_t)g * 32 + co2] = make_float2(xo0, xo1);
            if (g >= OFFF)
                *(float2*)&hob[(size_t)(g - OFFF) * 32 + co2] =
                    make_float2(hreg[j][0], hreg[j][1]);
        }
    }
}

// ---------------- skip sum: relu( sum_L SW_L @ h_L ) ---------------------------
__global__ void __launch_bounds__(256) skip_kernel(const float* __restrict__ sw)
{
    __shared__ __align__(16) float sws[32 * 272];   // [ci][so] padded
    __shared__ __align__(16) float hsm[64 * 32];    // [t][ci]

    int tid = threadIdx.x;
    int sx = tid & 31, ty = tid >> 5;
    int b   = blockIdx.y;
    int tf0 = blockIdx.x * 64;

    u64 acc[8][4];
#pragma unroll
    for (int i = 0; i < 8; i++)
#pragma unroll
        for (int j = 0; j < 4; j++) acc[i][j] = 0ull;

    for (int L = 0; L < NL; L++) {
        __syncthreads();
        const float* swb = sw + L * 8192;           // [so][ci]
        for (int idx = tid; idx < 8192; idx += 256) {
            int so = idx >> 5, ci = idx & 31;
            sws[ci * 272 + so] = swb[idx];
        }
        const float* hb = g_h + (size_t)(L * NB + b) * HSTR * NC + (size_t)tf0 * 32;
        for (int idx = tid; idx < 512; idx += 256) {
            int tt = idx >> 3, c4 = (idx & 7) * 4;
            float4 v = make_float4(0.f, 0.f, 0.f, 0.f);
            if (tf0 + tt < TFIN) v = *(const float4*)&hb[(size_t)tt * 32 + c4];
            *(float4*)&hsm[tt * 32 + c4] = v;
        }
        __syncthreads();
#pragma unroll 4
        for (int kk = 0; kk < 32; kk++) {
            float4 a0 = *(const float4*)&sws[kk * 272 + sx * 8];
            float4 a1 = *(const float4*)&sws[kk * 272 + sx * 8 + 4];
            float h0 = hsm[(ty * 8 + 0) * 32 + kk];
            float h1 = hsm[(ty * 8 + 1) * 32 + kk];
            float h2 = hsm[(ty * 8 + 2) * 32 + kk];
            float h3 = hsm[(ty * 8 + 3) * 32 + kk];
            float h4 = hsm[(ty * 8 + 4) * 32 + kk];
            float h5 = hsm[(ty * 8 + 5) * 32 + kk];
            float h6 = hsm[(ty * 8 + 6) * 32 + kk];
            float h7 = hsm[(ty * 8 + 7) * 32 + kk];
            u64 ap[8] = { pack1(a0.x), pack1(a0.y), pack1(a0.z), pack1(a0.w),
                          pack1(a1.x), pack1(a1.y), pack1(a1.z), pack1(a1.w) };
            u64 bp[4] = { pack2(h0, h1), pack2(h2, h3), pack2(h4, h5), pack2(h6, h7) };
#pragma unroll
            for (int jj = 0; jj < 8; jj++)
#pragma unroll
                for (int p = 0; p < 4; p++)
                    acc[jj][p] = fma2(ap[jj], bp[p], acc[jj][p]);
        }
    }
    float* skb = g_sk + (size_t)b * SKT * 256;
#pragma unroll
    for (int jj = 0; jj < 8; jj++) {
        int so = sx * 8 + jj;
#pragma unroll
        for (int p = 0; p < 4; p++) {
            float2 f = unpack2(acc[jj][p]);
            int t0 = tf0 + ty * 8 + 2 * p;
            if (t0     < TFIN) skb[(size_t)t0       * 256 + so] = fmaxf(f.x, 0.f);
            if (t0 + 1 < TFIN) skb[(size_t)(t0 + 1) * 256 + so] = fmaxf(f.y, 0.f);
        }
    }
}

// ---------------- fused end: out = W2 @ relu(W1 @ sk + b1) + b2 ----------------
__global__ void __launch_bounds__(256) end_kernel(
    const float* __restrict__ w1, const float* __restrict__ b1,
    const float* __restrict__ w2, const float* __restrict__ b2,
    float* __restrict__ out)
{
    extern __shared__ char smraw[];
    float* ws   = (float*)smraw;         // 32*272 [c][o]
    float* hsm  = ws + 32 * 272;         // 64*32  [t][c]
    float* mids = hsm + 64 * 32;         // 64*264 mid[t][o]; reused as trans[256][66]

    int tid = threadIdx.x;
    int sx = tid & 31, ty = tid >> 5;
    int b   = blockIdx.y;
    int tf0 = blockIdx.x * 64;

    u64 acc[8][4];
#pragma unroll
    for (int i = 0; i < 8; i++)
#pragma unroll
        for (int j = 0; j < 4; j++) acc[i][j] = 0ull;

    const float* skb = g_sk + (size_t)b * SKT * 256 + (size_t)tf0 * 256;

    // ---- phase A: mid = relu(W1 @ sk + b1)
    for (int c0 = 0; c0 < 256; c0 += 32) {
        __syncthreads();
        for (int idx = tid; idx < 8192; idx += 256) {
            int o = idx >> 5, c = idx & 31;
            ws[c * 272 + o] = w1[o * 256 + c0 + c];
        }
        for (int idx = tid; idx < 2048; idx += 256) {
            int tt = idx >> 5, ci = idx & 31;
            hsm[tt * 32 + ci] = (tf0 + tt < TFIN) ? skb[(size_t)tt * 256 + c0 + ci] : 0.f;
        }
        __syncthreads();
#pragma unroll 4
        for (int kk = 0; kk < 32; kk++) {
            float4 a0 = *(const float4*)&ws[kk * 272 + sx * 8];
            float4 a1 = *(const float4*)&ws[kk * 272 + sx * 8 + 4];
            float h0 = hsm[(ty * 8 + 0) * 32 + kk];
            float h1 = hsm[(ty * 8 + 1) * 32 + kk];
            float h2 = hsm[(ty * 8 + 2) * 32 + kk];
            float h3 = hsm[(ty * 8 + 3) * 32 + kk];
            float h4 = hsm[(ty * 8 + 4) * 32 + kk];
            float h5 = hsm[(ty * 8 + 5) * 32 + kk];
            float h6 = hsm[(ty * 8 + 6) * 32 + kk];
            float h7 = hsm[(ty * 8 + 7) * 32 + kk];
            u64 ap[8] = { pack1(a0.x), pack1(a0.y), pack1(a0.z), pack1(a0.w),
                          pack1(a1.x), pack1(a1.y), pack1(a1.z), pack1(a1.w) };
            u64 bp[4] = { pack2(h0, h1), pack2(h2, h3), pack2(h4, h5), pack2(h6, h7) };
#pragma unroll
            for (int jj = 0; jj < 8; jj++)
#pragma unroll
                for (int p = 0; p < 4; p++)
                    acc[jj][p] = fma2(ap[jj], bp[p], acc[jj][p]);
        }
    }
    __syncthreads();
#pragma unroll
    for (int jj = 0; jj < 8; jj++) {
        int o = sx * 8 + jj;
        float bias = b1[o];
#pragma unroll
        for (int p = 0; p < 4; p++) {
            float2 f = unpack2(acc[jj][p]);
            mids[(ty * 8 + 2 * p)     * 264 + o] = fmaxf(f.x + bias, 0.f);
            mids[(ty * 8 + 2 * p + 1) * 264 + o] = fmaxf(f.y + bias, 0.f);
        }
    }

    // ---- phase B: out = W2 @ mid + b2
    u64 acc2[8][4];
#pragma unroll
    for (int i = 0; i < 8; i++)
#pragma unroll
        for (int j = 0; j < 4; j++) acc2[i][j] = 0ull;

    for (int c0 = 0; c0 < 256; c0 += 32) {
        __syncthreads();
        for (int idx = tid; idx < 8192; idx += 256) {
            int o = idx >> 5, c = idx & 31;
            ws[c * 272 + o] = w2[o * 256 + c0 + c];
        }
        __syncthreads();
#pragma unroll 4
        for (int kk = 0; kk < 32; kk++) {
            float4 a0 = *(const float4*)&ws[kk * 272 + sx * 8];
            float4 a1 = *(const float4*)&ws[kk * 272 + sx * 8 + 4];
            int c = c0 + kk;
            float h0 = mids[(ty * 8 + 0) * 264 + c];
            float h1 = mids[(ty * 8 + 1) * 264 + c];
            float h2 = mids[(ty * 8 + 2) * 264 + c];
            float h3 = mids[(ty * 8 + 3) * 264 + c];
            float h4 = mids[(ty * 8 + 4) * 264 + c];
            float h5 = mids[(ty * 8 + 5) * 264 + c];
            float h6 = mids[(ty * 8 + 6) * 264 + c];
            float h7 = mids[(ty * 8 + 7) * 264 + c];
            u64 ap[8] = { pack1(a0.x), pack1(a0.y), pack1(a0.z), pack1(a0.w),
                          pack1(a1.x), pack1(a1.y), pack1(a1.z), pack1(a1.w) };
            u64 bp[4] = { pack2(h0, h1), pack2(h2, h3), pack2(h4, h5), pack2(h6, h7) };
#pragma unroll
            for (int jj = 0; jj < 8; jj++)
#pragma unroll
                for (int p = 0; p < 4; p++)
                    acc2[jj][p] = fma2(ap[jj], bp[p], acc2[jj][p]);
        }
    }
    // transpose via smem (mids is dead), then fully coalesced [b][o][t] stores
    __syncthreads();
    float* trans = mids;   // 256*66 = 16896 floats
#pragma unroll
    for (int jj = 0; jj < 8; jj++) {
        int o = sx * 8 + jj;
        float bias = b2[o];
#pragma unroll
        for (int p = 0; p < 4; p++) {
            float2 f = unpack2(acc2[jj][p]);
            trans[o * 66 + ty * 8 + 2 * p]     = f.x + bias;
            trans[o * 66 + ty * 8 + 2 * p + 1] = f.y + bias;
        }
    }
    __syncthreads();
    for (int idx = tid; idx < 16384; idx += 256) {
        int o = idx >> 6, t = idx & 63;
        if (tf0 + t < TFIN)
            out[((size_t)b * 256 + o) * TFIN + tf0 + t] = trans[o * 66 + t];
    }
}

#define END_SMEM ((32 * 272 + 64 * 32 + 64 * 264) * 4)

extern "C" void kernel_launch(void* const* d_in, const int* in_sizes, int n_in,
                              void* d_out, int out_size)
{
    const float* y   = (const float*)d_in[0];
    const float* cw  = (const float*)d_in[1];
    const float* cb  = (const float*)d_in[2];
    const float* fw  = (const float*)d_in[3];
    const float* gw  = (const float*)d_in[4];
    const float* rw  = (const float*)d_in[5];
    const float* sw  = (const float*)d_in[6];
    const float* e1w = (const float*)d_in[7];
    const float* e1b = (const float*)d_in[8];
    const float* e2w = (const float*)d_in[9];
    const float* e2b = (const float*)d_in[10];
    float* out = (float*)d_out;

    cudaFuncSetAttribute(end_kernel, cudaFuncAttributeMaxDynamicSharedMemorySize, END_SMEM);

    causal_kernel<<<(NB * T16K * NC + 255) / 256, 256>>>(y, cw, cb);

    int off = 0, parity = 0;
    for (int i = 0; i < NL; i++) {
        int d = 1 << (i % 10);
        off += d;
        int nbx = (T16K - off + LTILE - 1) / LTILE;
        layer_kernel<<<dim3(nbx, NB), 256>>>(fw, gw, rw, i, d, off, parity);
        parity ^= 1;
    }

    int ntf = (TFIN + 63) / 64;
    skip_kernel<<<dim3(ntf, NB), 256>>>(sw);
    end_kernel<<<dim3(ntf, NB), 256, END_SMEM>>>(e1w, e1b, e2w, e2b, out);
}

// round 5
// speedup vs baseline: 1.2583x; 1.0800x over previous
#include <cuda_runtime.h>

#define T16K 16384
#define NB 16
#define NC 32
#define NL 30
#define TFIN 13315        // 16384 - 3069
#define OFFF 3069         // total receptive field
#define HSTR 13344        // h time-stride (mult of 32)
#define SKT  13320        // sk time-stride
#define LTILE 128

typedef unsigned long long u64;

// ---------------- scratch (static device globals; allocation-free) -----------
__device__ float g_x0[(size_t)NB * T16K * NC];
__device__ float g_x1[(size_t)NB * T16K * NC];
__device__ float g_h [(size_t)NL * NB * HSTR * NC];   // [L][b][t][32]
__device__ float g_sk[(size_t)NB * SKT * 256];        // [b][t][256]

// ---------------- packed f32x2 helpers ---------------------------------------
__device__ __forceinline__ u64 pack2(float x, float y) {
    u64 r; asm("mov.b64 %0, {%1, %2};" : "=l"(r) : "f"(x), "f"(y)); return r;
}
__device__ __forceinline__ u64 pack1(float x) { return pack2(x, x); }
__device__ __forceinline__ u64 fma2(u64 a, u64 b, u64 c) {
    u64 d; asm("fma.rn.f32x2 %0, %1, %2, %3;" : "=l"(d) : "l"(a), "l"(b), "l"(c)); return d;
}
__device__ __forceinline__ float2 unpack2(u64 v) {
    float2 f; asm("mov.b64 {%0, %1}, %2;" : "=f"(f.x), "=f"(f.y) : "l"(v)); return f;
}
__device__ __forceinline__ float sigf(float x) {
    return __fdividef(1.f, 1.f + __expf(-x));
}
__device__ __forceinline__ float tanh_fast(float x) {
    return 1.f - __fdividef(2.f, 1.f + __expf(2.f * x));
}

// ---------------- causal 1x1 conv (1 -> 32 ch), channel-fastest out -----------
__global__ void causal_kernel(const float* __restrict__ y,
                              const float* __restrict__ cw,
                              const float* __restrict__ cb) {
    int idx = blockIdx.x * 256 + threadIdx.x;
    if (idx >= NB * T16K * NC) return;
    int c = idx & 31;
    int t = (idx >> 5) & (T16K - 1);
    int b = idx >> 19;
    g_x0[idx] = cw[c] * y[(b << 14) + t] + cb[c];
}

// ---------------- one WaveNet layer -------------------------------------------
// x layout [b][t][32]. Block: 128 t x 32 co; thread: 8t x 2co.
__global__ void __launch_bounds__(256) layer_kernel(
    const float* __restrict__ fw, const float* __restrict__ gw,
    const float* __restrict__ rw,
    int layer, int d, int off, int parity)
{
    extern __shared__ char smraw[];
    u64*   wfs = (u64*)smraw;          // [2][16*32] k-major
    u64*   wgs = wfs + 1024;
    u64*   wrs = wgs + 1024;           // [16*32]
    float* xs  = (float*)(wrs + 512);  // [128][32] x[g]
    float* xsd = xs + LTILE * 32;      // [128][32] x[g-d]; reused as h

    int tid = threadIdx.x;
    int b   = blockIdx.y;
    int g0  = off + blockIdx.x * LTILE;

    const float* xin  = parity ? g_x1 : g_x0;
    float*       xout = parity ? g_x0 : g_x1;

    // stage weights packed over ci-pairs: wfs[k][ci2*32+co] = {w[co][2ci2][k], w[co][2ci2+1][k]}
    const float* fwb = fw + layer * 2048;    // [co][ci][k]
    const float* gwb = gw + layer * 2048;
    for (int idx = tid; idx < 1024; idx += 256) {
        int co = idx & 31, ci2 = (idx >> 5) & 15, k = idx >> 9;
        int go = co * 64 + ci2 * 4 + k;
        wfs[k * 512 + ci2 * 32 + co] = pack2(fwb[go], fwb[go + 2]);
        wgs[k * 512 + ci2 * 32 + co] = pack2(gwb[go], gwb[go + 2]);
    }
    const float* rwb = rw + layer * 1024;    // [co][ci]
    for (int idx = tid; idx < 512; idx += 256) {
        int co = idx & 31, ci2 = idx >> 5;
        wrs[ci2 * 32 + co] = pack2(rwb[co * 32 + ci2 * 2], rwb[co * 32 + ci2 * 2 + 1]);
    }
    // stage x tiles (coalesced float4 rows)
    const float* xb = xin + (size_t)b * T16K * NC;
    for (int idx = tid; idx < 1024; idx += 256) {
        int tt = idx >> 3, c4 = (idx & 7) * 4;
        int g = g0 + tt;
        float4 v1 = make_float4(0.f, 0.f, 0.f, 0.f), v0 = v1;
        if (g < T16K) {
            v1 = *(const float4*)&xb[(size_t)g * 32 + c4];
            v0 = *(const float4*)&xb[(size_t)(g - d) * 32 + c4];
        }
        *(float4*)&xs [tt * 32 + c4] = v1;
        *(float4*)&xsd[tt * 32 + c4] = v0;
    }
    __syncthreads();

    int co2 = (tid & 15) * 2;
    int t8  = (tid >> 4) * 8;

    // ---- phase 1: filt/gate conv; 16B x loads cover 4 ci (= 2 ci-pairs)
    u64 af[8][2], ag[8][2];
#pragma unroll
    for (int j = 0; j < 8; j++) { af[j][0]=af[j][1]=ag[j][0]=ag[j][1]=0ull; }
#pragma unroll 2
    for (int ci4 = 0; ci4 < 8; ci4++) {
        int ia = ci4 * 64 + co2;         // ci2a = 2*ci4
        int ib = ia + 32;                // ci2b = 2*ci4+1
        ulonglong2 f0a = *(const ulonglong2*)&wfs[ia];
        ulonglong2 f0b = *(const ulonglong2*)&wfs[ib];
        ulonglong2 f1a = *(const ulonglong2*)&wfs[512 + ia];
        ulonglong2 f1b = *(const ulonglong2*)&wfs[512 + ib];
        ulonglong2 q0a = *(const ulonglong2*)&wgs[ia];
        ulonglong2 q0b = *(const ulonglong2*)&wgs[ib];
        ulonglong2 q1a = *(const ulonglong2*)&wgs[512 + ia];
        ulonglong2 q1b = *(const ulonglong2*)&wgs[512 + ib];
#pragma unroll
        for (int j = 0; j < 8; j++) {
            ulonglong2 x1 = *(const ulonglong2*)&xs [(t8 + j) * 32 + ci4 * 4];
            ulonglong2 x0 = *(const ulonglong2*)&xsd[(t8 + j) * 32 + ci4 * 4];
            af[j][0] = fma2(f0a.x, x0.x, af[j][0]);
            af[j][0] = fma2(f1a.x, x1.x, af[j][0]);
            af[j][0] = fma2(f0b.x, x0.y, af[j][0]);
            af[j][0] = fma2(f1b.x, x1.y, af[j][0]);
            af[j][1] = fma2(f0a.y, x0.x, af[j][1]);
            af[j][1] = fma2(f1a.y, x1.x, af[j][1]);
            af[j][1] = fma2(f0b.y, x0.y, af[j][1]);
            af[j][1] = fma2(f1b.y, x1.y, af[j][1]);
            ag[j][0] = fma2(q0a.x, x0.x, ag[j][0]);
            ag[j][0] = fma2(q1a.x, x1.x, ag[j][0]);
            ag[j][0] = fma2(q0b.x, x0.y, ag[j][0]);
            ag[j][0] = fma2(q1b.x, x1.y, ag[j][0]);
            ag[j][1] = fma2(q0a.y, x0.x, ag[j][1]);
            ag[j][1] = fma2(q1a.y, x1.x, ag[j][1]);
            ag[j][1] = fma2(q0b.y, x0.y, ag[j][1]);
            ag[j][1] = fma2(q1b.y, x1.y, ag[j][1]);
        }
    }
    float hreg[8][2];
#pragma unroll
    for (int j = 0; j < 8; j++)
#pragma unroll
        for (int c = 0; c < 2; c++) {
            float2 fv = unpack2(af[j][c]);
            float2 gv = unpack2(ag[j][c]);
            hreg[j][c] = tanh_fast(fv.x + fv.y) * sigf(gv.x + gv.y);
        }
    __syncthreads();                // all reads of xsd done
    float* hs = xsd;                // reuse as h buffer
#pragma unroll
    for (int j = 0; j < 8; j++)
        *(float2*)&hs[(t8 + j) * 32 + co2] = make_float2(hreg[j][0], hreg[j][1]);
    __syncthreads();

    // ---- phase 2: res 1x1 conv + residual
    u64 ar[8][2];
#pragma unroll
    for (int j = 0; j < 8; j++) { ar[j][0]=ar[j][1]=0ull; }
#pragma unroll 4
    for (int ci4 = 0; ci4 < 8; ci4++) {
        ulonglong2 wa = *(const ulonglong2*)&wrs[ci4 * 64 + co2];
        ulonglong2 wb = *(const ulonglong2*)&wrs[ci4 * 64 + 32 + co2];
#pragma unroll
        for (int j = 0; j < 8; j++) {
            ulonglong2 hv = *(const ulonglong2*)&hs[(t8 + j) * 32 + ci4 * 4];
            ar[j][0] = fma2(wa.x, hv.x, ar[j][0]);
            ar[j][0] = fma2(wb.x, hv.y, ar[j][0]);
            ar[j][1] = fma2(wa.y, hv.x, ar[j][1]);
            ar[j][1] = fma2(wb.y, hv.y, ar[j][1]);
        }
    }
    float* xob = xout + (size_t)b * T16K * NC;
    float* hob = g_h + (size_t)(layer * NB + b) * HSTR * NC;
#pragma unroll
    for (int j = 0; j < 8; j++) {
        int g = g0 + t8 + j;
        if (g < T16K) {
            float2 r0 = unpack2(ar[j][0]);
            float2 r1 = unpack2(ar[j][1]);
            float2 xv = *(const float2*)&xs[(t8 + j) * 32 + co2];
            *(float2*)&xob[(size_t)g * 32 + co2] =
                make_float2(xv.x + r0.x + r0.y, xv.y + r1.x + r1.y);
            if (g >= OFFF)
                *(float2*)&hob[(size_t)(g - OFFF) * 32 + co2] =
                    make_float2(hreg[j][0], hreg[j][1]);
        }
    }
}

// ---------------- skip sum: relu( sum_L SW_L @ h_L ) ---------------------------
// Block tile: 64 so x 256 t. Thread: 8 so x 8 t. sog=tid&7, tg=tid>>3.
__global__ void __launch_bounds__(256) skip_kernel(const float* __restrict__ sw)
{
    __shared__ __align__(16) float sws[32 * 68];    // [ci][so 64 pad]
    __shared__ __align__(16) float hsm[256 * 32];   // [t][ci]

    int tid = threadIdx.x;
    int sog = tid & 7, tg = tid >> 3;
    int b   = blockIdx.z;
    int so0 = blockIdx.y * 64;
    int tf0 = blockIdx.x * 256;

    u64 acc[8][4];
#pragma unroll
    for (int i = 0; i < 8; i++)
#pragma unroll
        for (int j = 0; j < 4; j++) acc[i][j] = 0ull;

    for (int L = 0; L < NL; L++) {
        __syncthreads();
        const float* swb = sw + L * 8192 + so0 * 32;   // [so][ci]
        for (int idx = tid; idx < 2048; idx += 256) {
            int so = idx >> 5, ci = idx & 31;
            sws[ci * 68 + so] = swb[so * 32 + ci];
        }
        const float* hb = g_h + (size_t)(L * NB + b) * HSTR * NC + (size_t)tf0 * 32;
        for (int idx = tid; idx < 2048; idx += 256) {
            int tt = idx >> 3, c4 = (idx & 7) * 4;
            float4 v = make_float4(0.f, 0.f, 0.f, 0.f);
            if (tf0 + tt < TFIN) v = *(const float4*)&hb[(size_t)tt * 32 + c4];
            *(float4*)&hsm[tt * 32 + c4] = v;
        }
        __syncthreads();
#pragma unroll 4
        for (int kk = 0; kk < 32; kk++) {
            float4 a0 = *(const float4*)&sws[kk * 68 + sog * 8];
            float4 a1 = *(const float4*)&sws[kk * 68 + sog * 8 + 4];
            float h0 = hsm[(tg * 8 + 0) * 32 + kk];
            float h1 = hsm[(tg * 8 + 1) * 32 + kk];
            float h2 = hsm[(tg * 8 + 2) * 32 + kk];
            float h3 = hsm[(tg * 8 + 3) * 32 + kk];
            float h4 = hsm[(tg * 8 + 4) * 32 + kk];
            float h5 = hsm[(tg * 8 + 5) * 32 + kk];
            float h6 = hsm[(tg * 8 + 6) * 32 + kk];
            float h7 = hsm[(tg * 8 + 7) * 32 + kk];
            u64 ap[8] = { pack1(a0.x), pack1(a0.y), pack1(a0.z), pack1(a0.w),
                          pack1(a1.x), pack1(a1.y), pack1(a1.z), pack1(a1.w) };
            u64 bp[4] = { pack2(h0, h1), pack2(h2, h3), pack2(h4, h5), pack2(h6, h7) };
#pragma unroll
            for (int jj = 0; jj < 8; jj++)
#pragma unroll
                for (int p = 0; p < 4; p++)
                    acc[jj][p] = fma2(ap[jj], bp[p], acc[jj][p]);
        }
    }
    float* skb = g_sk + (size_t)b * SKT * 256;
#pragma unroll
    for (int p = 0; p < 4; p++) {
        float2 f[8];
#pragma unroll
        for (int jj = 0; jj < 8; jj++) f[jj] = unpack2(acc[jj][p]);
        int t0 = tf0 + tg * 8 + 2 * p;
        if (t0 < TFIN) {
            *(float4*)&skb[(size_t)t0 * 256 + so0 + sog * 8] =
                make_float4(fmaxf(f[0].x,0.f), fmaxf(f[1].x,0.f), fmaxf(f[2].x,0.f), fmaxf(f[3].x,0.f));
            *(float4*)&skb[(size_t)t0 * 256 + so0 + sog * 8 + 4] =
                make_float4(fmaxf(f[4].x,0.f), fmaxf(f[5].x,0.f), fmaxf(f[6].x,0.f), fmaxf(f[7].x,0.f));
        }
        if (t0 + 1 < TFIN) {
            *(float4*)&skb[(size_t)(t0+1) * 256 + so0 + sog * 8] =
                make_float4(fmaxf(f[0].y,0.f), fmaxf(f[1].y,0.f), fmaxf(f[2].y,0.f), fmaxf(f[3].y,0.f));
            *(float4*)&skb[(size_t)(t0+1) * 256 + so0 + sog * 8 + 4] =
                make_float4(fmaxf(f[4].y,0.f), fmaxf(f[5].y,0.f), fmaxf(f[6].y,0.f), fmaxf(f[7].y,0.f));
        }
    }
}

// ---------------- fused end: out = W2 @ relu(W1 @ sk + b1) + b2 ----------------
// Block: 256 o x 64 t. Thread: 8 o x 8 t. tg=tid&7, og=tid>>3.
__global__ void __launch_bounds__(256) end_kernel(
    const float* __restrict__ w1, const float* __restrict__ b1,
    const float* __restrict__ w2, const float* __restrict__ b2,
    float* __restrict__ out)
{
    extern __shared__ char smraw[];
    float* ws  = (float*)smraw;          // [32][260]  weight slice [c][o]
    float* hsm = ws + 32 * 260;          // [64][32]   sk slice [t][c]
    float* mid = hsm + 64 * 32;          // [256][68]  mid[o][t]

    int tid = threadIdx.x;
    int tg = tid & 7, og = tid >> 3;
    int b   = blockIdx.y;
    int tf0 = blockIdx.x * 64;

    const float* skb = g_sk + (size_t)b * SKT * 256 + (size_t)tf0 * 256;

    // ---- phase A: mid = relu(W1 @ sk + b1)
    u64 acc[8][4];
#pragma unroll
    for (int i = 0; i < 8; i++)
#pragma unroll
        for (int j = 0; j < 4; j++) acc[i][j] = 0ull;

    for (int c0 = 0; c0 < 256; c0 += 32) {
        __syncthreads();
        for (int idx = tid; idx < 8192; idx += 256) {
            int o = idx >> 5, c = idx & 31;
            ws[c * 260 + o] = w1[o * 256 + c0 + c];
        }
        for (int idx = tid; idx < 512; idx += 256) {
            int tt = idx >> 3, c4 = (idx & 7) * 4;
            float4 v = make_float4(0.f, 0.f, 0.f, 0.f);
            if (tf0 + tt < TFIN) v = *(const float4*)&skb[(size_t)tt * 256 + c0 + c4];
            *(float4*)&hsm[tt * 32 + c4] = v;
        }
        __syncthreads();
#pragma unroll 4
        for (int kk = 0; kk < 32; kk++) {
            float4 a0 = *(const float4*)&ws[kk * 260 + og * 8];
            float4 a1 = *(const float4*)&ws[kk * 260 + og * 8 + 4];
            float h0 = hsm[(tg * 8 + 0) * 32 + kk];
            float h1 = hsm[(tg * 8 + 1) * 32 + kk];
            float h2 = hsm[(tg * 8 + 2) * 32 + kk];
            float h3 = hsm[(tg * 8 + 3) * 32 + kk];
            float h4 = hsm[(tg * 8 + 4) * 32 + kk];
            float h5 = hsm[(tg * 8 + 5) * 32 + kk];
            float h6 = hsm[(tg * 8 + 6) * 32 + kk];
            float h7 = hsm[(tg * 8 + 7) * 32 + kk];
            u64 ap[8] = { pack1(a0.x), pack1(a0.y), pack1(a0.z), pack1(a0.w),
                          pack1(a1.x), pack1(a1.y), pack1(a1.z), pack1(a1.w) };
            u64 bp[4] = { pack2(h0, h1), pack2(h2, h3), pack2(h4, h5), pack2(h6, h7) };
#pragma unroll
            for (int jj = 0; jj < 8; jj++)
#pragma unroll
                for (int p = 0; p < 4; p++)
                    acc[jj][p] = fma2(ap[jj], bp[p], acc[jj][p]);
        }
    }
    // bias + relu -> mid[o][t]
#pragma unroll
    for (int jj = 0; jj < 8; jj++) {
        int o = og * 8 + jj;
        float bias = b1[o];
#pragma unroll
        for (int p = 0; p < 4; p++) {
            float2 f = unpack2(acc[jj][p]);
            mid[o * 68 + tg * 8 + 2 * p]     = fmaxf(f.x + bias, 0.f);
            mid[o * 68 + tg * 8 + 2 * p + 1] = fmaxf(f.y + bias, 0.f);
        }
    }

    // ---- phase B: out = W2 @ mid + b2
    u64 acc2[8][4];
#pragma unroll
    for (int i = 0; i < 8; i++)
#pragma unroll
        for (int j = 0; j < 4; j++) acc2[i][j] = 0ull;

    for (int c0 = 0; c0 < 256; c0 += 32) {
        __syncthreads();    // also covers mid writes on first iteration
        for (int idx = tid; idx < 8192; idx += 256) {
            int o = idx >> 5, c = idx & 31;
            ws[c * 260 + o] = w2[o * 256 + c0 + c];
        }
        __syncthreads();
#pragma unroll 4
        for (int kk = 0; kk < 32; kk++) {
            float4 a0 = *(const float4*)&ws[kk * 260 + og * 8];
            float4 a1 = *(const float4*)&ws[kk * 260 + og * 8 + 4];
            float4 m0 = *(const float4*)&mid[(c0 + kk) * 68 + tg * 8];
            float4 m1 = *(const float4*)&mid[(c0 + kk) * 68 + tg * 8 + 4];
            u64 ap[8] = { pack1(a0.x), pack1(a0.y), pack1(a0.z), pack1(a0.w),
                          pack1(a1.x), pack1(a1.y), pack1(a1.z), pack1(a1.w) };
            u64 bp[4] = { pack2(m0.x, m0.y), pack2(m0.z, m0.w),
                          pack2(m1.x, m1.y), pack2(m1.z, m1.w) };
#pragma unroll
            for (int jj = 0; jj < 8; jj++)
#pragma unroll
                for (int p = 0; p < 4; p++)
                    acc2[jj][p] = fma2(ap[jj], bp[p], acc2[jj][p]);
        }
    }
    // bias + store [b][o][t]
#pragma unroll
    for (int jj = 0; jj < 8; jj++) {
        int o = og * 8 + jj;
        float bias = b2[o];
        float* ob = out + ((size_t)b * 256 + o) * TFIN;
#pragma unroll
        for (int p = 0; p < 4; p++) {
            float2 f = unpack2(acc2[jj][p]);
            int t = tf0 + tg * 8 + 2 * p;
            if (t < TFIN)     ob[t]     = f.x + bias;
            if (t + 1 < TFIN) ob[t + 1] = f.y + bias;
        }
    }
}

#define LAYER_SMEM ((1024 + 1024 + 512) * 8 + 2 * LTILE * 32 * 4)
#define END_SMEM   ((32 * 260 + 64 * 32 + 256 * 68) * 4)

extern "C" void kernel_launch(void* const* d_in, const int* in_sizes, int n_in,
                              void* d_out, int out_size)
{
    const float* y   = (const float*)d_in[0];
    const float* cw  = (const float*)d_in[1];
    const float* cb  = (const float*)d_in[2];
    const float* fw  = (const float*)d_in[3];
    const float* gw  = (const float*)d_in[4];
    const float* rw  = (const float*)d_in[5];
    const float* sw  = (const float*)d_in[6];
    const float* e1w = (const float*)d_in[7];
    const float* e1b = (const float*)d_in[8];
    const float* e2w = (const float*)d_in[9];
    const float* e2b = (const float*)d_in[10];
    float* out = (float*)d_out;

    cudaFuncSetAttribute(layer_kernel, cudaFuncAttributeMaxDynamicSharedMemorySize, LAYER_SMEM);
    cudaFuncSetAttribute(end_kernel,   cudaFuncAttributeMaxDynamicSharedMemorySize, END_SMEM);

    causal_kernel<<<(NB * T16K * NC + 255) / 256, 256>>>(y, cw, cb);

    int off = 0, parity = 0;
    for (int i = 0; i < NL; i++) {
        int d = 1 << (i % 10);
        off += d;
        int nbx = (T16K - off + LTILE - 1) / LTILE;
        layer_kernel<<<dim3(nbx, NB), 256, LAYER_SMEM>>>(fw, gw, rw, i, d, off, parity);
        parity ^= 1;
    }

    int nt_sk = (TFIN + 255) / 256;
    skip_kernel<<<dim3(nt_sk, 4, NB), 256>>>(sw);

    int nt_end = (TFIN + 63) / 64;
    end_kernel<<<dim3(nt_end, NB), 256, END_SMEM>>>(e1w, e1b, e2w, e2b, out);
}